// round 1
// baseline (speedup 1.0000x reference)
#include <cuda_runtime.h>

#define Wd 512
#define BATCH 16
#define NPIX (Wd * Wd)
#define NTOT (BATCH * NPIX)
#define CELL_Wf 0.390625f   /* 200/512, exact in fp32 */

__device__ float g_terrA[NTOT];
__device__ float g_terrB[NTOT];
__device__ float g_sed[NTOT];
__device__ float g_wat[NTOT];
__device__ float g_vel[NTOT];

__global__ void init_kernel(const float* __restrict__ in) {
    int idx = blockIdx.x * blockDim.x + threadIdx.x;
    if (idx >= NTOT) return;
    g_terrA[idx] = (1.0f - in[idx]) * 0.5f;
    g_sed[idx] = 0.0f;
    g_wat[idx] = 0.0f;
    g_vel[idx] = 0.0f;
}

__device__ __forceinline__ float gat(const float* __restrict__ t, int ix, int iy) {
    if (ix < 0 || ix > Wd - 1 || iy < 0 || iy > Wd - 1) return 0.0f;
    return t[iy * Wd + ix] - 1.0f;
}

template <bool LAST>
__global__ void step_kernel(const float* __restrict__ tin,
                            float* __restrict__ tout,
                            const float* __restrict__ rain,
                            const float* __restrict__ p_rain_rate,
                            const float* __restrict__ p_evap,
                            const float* __restrict__ p_minhd,
                            const float* __restrict__ p_heps,
                            const float* __restrict__ p_grav,
                            const float* __restrict__ p_kc,
                            const float* __restrict__ p_dis,
                            const float* __restrict__ p_dep) {
    int idx = blockIdx.x * blockDim.x + threadIdx.x;
    if (idx >= NTOT) return;
    int rem = idx & (NPIX - 1);
    int i = rem >> 9;        // row (axis 1)
    int j = rem & (Wd - 1);  // col (axis 2)
    const float* t = tin + (idx - rem);  // this batch's terrain plane

    float tc = t[rem];

    // simple_gradient: dx along rows (axis 1), dy along cols (axis 2),
    // with reference's exact boundary forms (t*1.1 - t) / (t*0.9 - t).
    float dx;
    if (i == 0)            dx = 0.5f * (tc * 1.1f - tc);
    else if (i == Wd - 1)  dx = 0.5f * (tc * 0.9f - tc);
    else                   dx = 0.5f * (t[rem + Wd] - t[rem - Wd]);
    float dy;
    if (j == 0)            dy = 0.5f * (tc * 1.1f - tc);
    else if (j == Wd - 1)  dy = 0.5f * (tc * 0.9f - tc);
    else                   dy = 0.5f * (t[rem + 1] - t[rem - 1]);

    float mag = sqrtf(dx * dx + dy * dy + 1e-11f);
    // factor = relu(1e-10 - mag) == 0 always (mag >= 3.16e-6), so:
    float fdx = dx / mag;
    float fdy = dy / mag;

    // bilinear_sample(terrain, -gradient): fx along cols uses fdx, fy along rows uses fdy
    float fx = (float)j - fdx;
    float fy = (float)i - fdy;
    float x0 = floorf(fx), y0 = floorf(fy);
    float wx = fx - x0, wy = fy - y0;
    int ix0 = (int)x0, iy0 = (int)y0;
    float g00 = gat(t, ix0,     iy0);
    float g10 = gat(t, ix0 + 1, iy0);
    float g01 = gat(t, ix0,     iy0 + 1);
    float g11 = gat(t, ix0 + 1, iy0 + 1);
    float neighbor = (1.0f - wy) * ((1.0f - wx) * g00 + wx * g10)
                   + wy          * ((1.0f - wx) * g01 + wx * g11) + 1.0f;

    float hd = tc - neighbor;
    float heps  = *p_heps;
    float minhd = *p_minhd;

    // hds = sign(relu(hd - heps)) -> 1 if hd - heps > 0 else 0
    float hds = (hd - heps) > 0.0f ? 1.0f : 0.0f;
    float nhd = hds * fmaxf(hd, minhd);

    float w = g_wat[idx] + fmaxf(*p_rain_rate, 0.0f) * rain[rem];
    float v = g_vel[idx];
    float s = g_sed[idx];

    float sed_cap = nhd / CELL_Wf * v * w * fmaxf(*p_kc, 0.0f);
    float ftb = (hd < 0.0f) ? 1.0f : 0.0f;  // relu(sign(-hd))
    float first = fminf(fmaxf(-hd, 0.0f), s);
    float sdiff = s - sed_cap;
    float third = (1.0f - ftb)
                * (fmaxf(sdiff * (*p_dep), 0.0f) - fmaxf(-sdiff * (*p_dis), 0.0f));
    float dep = fmaxf(-fmaxf(hd, 0.0f), first + third);

    float s2 = s - dep;
    float t2 = tc + dep;

    // displace(a, gradient): local 3-term sum, t1 zeroed at last col, t3 at first col
    float r1 = fmaxf(-fdy, 0.0f);
    float r2 = fmaxf(1.0f - fabsf(fdy), 0.0f);
    float r3 = fmaxf(fdy, 0.0f);
    float d1 = (j == Wd - 1) ? 0.0f : r1;
    float d3 = (j == 0)      ? 0.0f : r3;

    g_sed[idx] = d1 * s2 + r2 * s2 + d3 * s2;
    float wdisp = d1 * w + r2 * w + d3 * w;
    g_wat[idx] = wdisp * (1.0f - fmaxf(*p_evap, 0.0f));
    g_vel[idx] = fmaxf(*p_grav, 0.0f) * hd / CELL_Wf;

    if (LAST) {
        // relu(1 + (1 - terrain*2)) - 1
        tout[idx] = fmaxf(1.0f + (1.0f - t2 * 2.0f), 0.0f) - 1.0f;
    } else {
        tout[idx] = t2;
    }
}

extern "C" void kernel_launch(void* const* d_in, const int* in_sizes, int n_in,
                              void* d_out, int out_size) {
    const float* input     = (const float*)d_in[0];
    const float* rainall   = (const float*)d_in[1];
    // d_in[2] (random_gradient) is provably unused: factor == 0 in fp32.
    const float* rain_rate = (const float*)d_in[3];
    const float* evap      = (const float*)d_in[4];
    const float* minhd     = (const float*)d_in[5];
    const float* heps      = (const float*)d_in[6];
    const float* grav      = (const float*)d_in[7];
    const float* kc        = (const float*)d_in[8];
    const float* dis       = (const float*)d_in[9];
    const float* depr      = (const float*)d_in[10];
    float* out = (float*)d_out;

    float *tA, *tB;
    cudaGetSymbolAddress((void**)&tA, g_terrA);
    cudaGetSymbolAddress((void**)&tB, g_terrB);

    dim3 blk(256), grd(NTOT / 256);
    init_kernel<<<grd, blk>>>(input);

    for (int it = 0; it < 10; ++it) {
        const float* tin = (it & 1) ? tB : tA;
        float* tout      = (it & 1) ? tA : tB;
        const float* rain = rainall + (size_t)it * NPIX;
        if (it == 9) {
            step_kernel<true><<<grd, blk>>>(tin, out, rain, rain_rate, evap,
                                            minhd, heps, grav, kc, dis, depr);
        } else {
            step_kernel<false><<<grd, blk>>>(tin, tout, rain, rain_rate, evap,
                                             minhd, heps, grav, kc, dis, depr);
        }
    }
}

// round 2
// speedup vs baseline: 2.4570x; 2.4570x over previous
#include <cuda_runtime.h>

#define Wd 512
#define BATCH 16
#define NPIX (Wd * Wd)
#define NTOT (BATCH * NPIX)
#define PADW 520
#define PADH 516
#define PADN (PADW * PADH)
#define INV_CELL 2.56f  /* 1 / (200/512) */

// Padded tm1 (= terrain - 1) buffers, zero borders (2 rows top, 2+ bottom, 4 cols left, 4 right).
// Logical (i,j) lives at pad[(i+2)*PADW + (j+4)].
__device__ __align__(16) float g_padA[BATCH * PADN];
__device__ __align__(16) float g_padB[BATCH * PADN];
__device__ __align__(16) float g_sed[NTOT];
__device__ __align__(16) float g_wat[NTOT];
__device__ __align__(16) float g_vel[NTOT];
__device__ float g_par[8];

__global__ void param_kernel(const float* rr, const float* ev, const float* mh,
                             const float* he, const float* gr, const float* kc,
                             const float* di, const float* de) {
    g_par[0] = fmaxf(*rr, 0.0f);            // relu(rain_rate)
    g_par[1] = *he;                         // height_epsilon
    g_par[2] = *mh;                         // min_height_delta
    g_par[3] = fmaxf(*kc, 0.0f) * INV_CELL; // relu(kc)/CELL_W
    g_par[4] = *di;                         // dissolving_rate
    g_par[5] = *de;                         // deposition_rate
    g_par[6] = 1.0f - fmaxf(*ev, 0.0f);     // 1 - relu(evap)
    g_par[7] = fmaxf(*gr, 0.0f) * INV_CELL; // relu(g)/CELL_W
}

__global__ void init_kernel(const float* __restrict__ in) {
    int row = blockIdx.x;            // 0 .. BATCH*PADH-1
    int b = row / PADH;
    int pi = row - b * PADH;
    int pj = threadIdx.x;            // 0 .. 519
    int pidx = b * PADN + pi * PADW + pj;
    float v = 0.0f;
    if (pi >= 2 && pi < 2 + Wd && pj >= 4 && pj < 4 + Wd) {
        int i = pi - 2, j = pj - 4;
        int cidx = b * NPIX + i * Wd + j;
        float t0 = (1.0f - in[cidx]) * 0.5f;
        v = t0 - 1.0f;                       // exactly the reference's tm1
        g_sed[cidx] = 0.0f;
        g_wat[cidx] = 0.0f;
        g_vel[cidx] = 0.0f;
    }
    g_padA[pidx] = v;
    g_padB[pidx] = 0.0f;  // borders of B must also be zero; interior overwritten each step
}

template <bool LAST>
__global__ void __launch_bounds__(128)
step_kernel(const float* __restrict__ pin, float* __restrict__ pout,
            const float* __restrict__ rain, float* __restrict__ outp) {
    int blk = blockIdx.x;          // = b*Wd + i
    int i = blk & (Wd - 1);
    int b = blk >> 9;
    int j0 = threadIdx.x << 2;     // 4 pixels per thread

    const float4* parv = reinterpret_cast<const float4*>(g_par);
    float4 pA = parv[0];  // x=rain_rate' y=heps z=minhd w=kc'
    float4 pB = parv[1];  // x=dis y=dep z=evap' w=grav'

    const float* pbat = pin + b * PADN;
    const float* prow = pbat + (i + 2) * PADW;   // padded center row
    const float* pint = pbat + 2 * PADW + 4;     // logical (0,0)

    float4 c4 = *reinterpret_cast<const float4*>(prow + 4 + j0);
    float pl = prow[3 + j0];   // j0-1 (zero pad when j0==0; unused there)
    float pr = prow[8 + j0];   // j0+4 (zero pad when j0==508; unused there)

    float cv[4] = {c4.x, c4.y, c4.z, c4.w};
    float lv[4] = {pl, c4.x, c4.y, c4.z};
    float rv[4] = {c4.y, c4.z, c4.w, pr};

    float dxv[4];
    if (i > 0 && i < Wd - 1) {
        float4 u4 = *reinterpret_cast<const float4*>(prow - PADW + 4 + j0);
        float4 d4 = *reinterpret_cast<const float4*>(prow + PADW + 4 + j0);
        dxv[0] = 0.5f * (d4.x - u4.x);
        dxv[1] = 0.5f * (d4.y - u4.y);
        dxv[2] = 0.5f * (d4.z - u4.z);
        dxv[3] = 0.5f * (d4.w - u4.w);
    } else {
        float sc = (i == 0) ? 1.1f : 0.9f;
#pragma unroll
        for (int k = 0; k < 4; ++k) {
            float t = cv[k] + 1.0f;
            dxv[k] = 0.5f * (t * sc - t);
        }
    }

    int cidx = b * NPIX + i * Wd + j0;
    float4 s4  = *reinterpret_cast<const float4*>(g_sed + cidx);
    float4 w4  = *reinterpret_cast<const float4*>(g_wat + cidx);
    float4 v4  = *reinterpret_cast<const float4*>(g_vel + cidx);
    float4 rn4 = *reinterpret_cast<const float4*>(rain + i * Wd + j0);
    float sv[4] = {s4.x, s4.y, s4.z, s4.w};
    float wv[4] = {w4.x, w4.y, w4.z, w4.w};
    float vv[4] = {v4.x, v4.y, v4.z, v4.w};
    float rnv[4] = {rn4.x, rn4.y, rn4.z, rn4.w};

    float so[4], wo[4], vo[4], to[4];

#pragma unroll
    for (int k = 0; k < 4; ++k) {
        float tcm = cv[k];
        float tcf = tcm + 1.0f;
        float dx = dxv[k];

        float dy = 0.5f * (rv[k] - lv[k]);
        if (k == 0 && j0 == 0)        dy = 0.5f * (tcf * 1.1f - tcf);
        if (k == 3 && j0 == Wd - 4)   dy = 0.5f * (tcf * 0.9f - tcf);

        float rinv = rsqrtf(dx * dx + dy * dy + 1e-11f);
        float fdx = dx * rinv;
        float fdy = dy * rinv;

        int jj = j0 + k;
        float fx = (float)jj - fdx;
        float fy = (float)i  - fdy;
        float x0 = floorf(fx), y0 = floorf(fy);
        float wx = fx - x0, wy = fy - y0;
        int ix = (int)x0, iy = (int)y0;

        const float* g = pint + iy * PADW + ix;   // unconditional, zero-padded
        float g00 = g[0];
        float g10 = g[1];
        float g01 = g[PADW];
        float g11 = g[PADW + 1];
        float nb = (1.0f - wy) * ((1.0f - wx) * g00 + wx * g10)
                 + wy          * ((1.0f - wx) * g01 + wx * g11) + 1.0f;

        float hd = tcf - nb;
        float nhd = (hd > pA.y) ? fmaxf(hd, pA.z) : 0.0f;

        float w = wv[k] + pA.x * rnv[k];
        float scap = nhd * pA.w * vv[k] * w;
        float first = fminf(fmaxf(-hd, 0.0f), sv[k]);
        float sdiff = sv[k] - scap;
        float third = (hd < 0.0f) ? 0.0f
                    : (fmaxf(sdiff * pB.y, 0.0f) - fmaxf(-sdiff * pB.x, 0.0f));
        float dep = fmaxf(-fmaxf(hd, 0.0f), first + third);

        float s2 = sv[k] - dep;
        float t2 = tcf + dep;

        float ad = fabsf(fdy);
        float r2v = fmaxf(1.0f - ad, 0.0f);
        float fac = ad + r2v;                       // r1 + r2 + r3 (one of r1,r3 is 0)
        if (k == 0 && j0 == 0)      fac = fmaxf(-fdy, 0.0f) + r2v;  // t3 zeroed at col 0
        if (k == 3 && j0 == Wd - 4) fac = r2v + fmaxf(fdy, 0.0f);   // t1 zeroed at col W-1

        so[k] = fac * s2;
        wo[k] = (fac * w) * pB.z;
        vo[k] = pB.w * hd;
        to[k] = LAST ? (fmaxf(1.0f + (1.0f - t2 * 2.0f), 0.0f) - 1.0f)
                     : (t2 - 1.0f);
    }

    *reinterpret_cast<float4*>(g_sed + cidx) = make_float4(so[0], so[1], so[2], so[3]);
    *reinterpret_cast<float4*>(g_wat + cidx) = make_float4(wo[0], wo[1], wo[2], wo[3]);
    *reinterpret_cast<float4*>(g_vel + cidx) = make_float4(vo[0], vo[1], vo[2], vo[3]);
    if (LAST) {
        *reinterpret_cast<float4*>(outp + cidx) = make_float4(to[0], to[1], to[2], to[3]);
    } else {
        float* porow = pout + b * PADN + (i + 2) * PADW + 4 + j0;
        *reinterpret_cast<float4*>(porow) = make_float4(to[0], to[1], to[2], to[3]);
    }
}

extern "C" void kernel_launch(void* const* d_in, const int* in_sizes, int n_in,
                              void* d_out, int out_size) {
    const float* input     = (const float*)d_in[0];
    const float* rainall   = (const float*)d_in[1];
    // d_in[2] (random_gradient) provably unused: factor == relu(1e-10 - mag) == 0 in fp32.
    const float* rain_rate = (const float*)d_in[3];
    const float* evap      = (const float*)d_in[4];
    const float* minhd     = (const float*)d_in[5];
    const float* heps      = (const float*)d_in[6];
    const float* grav      = (const float*)d_in[7];
    const float* kc        = (const float*)d_in[8];
    const float* dis       = (const float*)d_in[9];
    const float* depr      = (const float*)d_in[10];
    float* out = (float*)d_out;

    float *pA, *pB;
    cudaGetSymbolAddress((void**)&pA, g_padA);
    cudaGetSymbolAddress((void**)&pB, g_padB);

    param_kernel<<<1, 1>>>(rain_rate, evap, minhd, heps, grav, kc, dis, depr);
    init_kernel<<<BATCH * PADH, PADW>>>(input);

    for (int it = 0; it < 10; ++it) {
        const float* pin = (it & 1) ? pB : pA;
        float* pout      = (it & 1) ? pA : pB;
        const float* rain = rainall + (size_t)it * NPIX;
        if (it == 9) {
            step_kernel<true><<<BATCH * Wd, 128>>>(pin, pout, rain, out);
        } else {
            step_kernel<false><<<BATCH * Wd, 128>>>(pin, pout, rain, out);
        }
    }
}